// round 2
// baseline (speedup 1.0000x reference)
#include <cuda_runtime.h>
#include <math.h>

// Problem constants
#define Bz 4
#define Cz 12
#define Hh 256
#define Ww 256
#define HW 65536            // Hh*Ww
#define NMASK 96            // 2*Bz*Cz
#define HALFM 48            // Bz*Cz
#define LARGEF 1000000.0f

// ---------------- scratch (static device globals; no allocations) ------------
__device__ unsigned char g_mask[NMASK * HW];     // 6.3 MB
__device__ float2        g_a[NMASK * HW];        // 50 MB: per pixel {a_fg, a_bg} = g^2 + w^2
__device__ float         g_field[NMASK * HW];    // 25 MB
__device__ int           g_hasfg[NMASK];
__device__ double        g_acc[2];               // [0]=hausdorff sum, [1]=sum logp_t
__device__ int           g_is64;

// ---------------- K0: zero accumulators + detect target dtype ----------------
__global__ void k0_init(const unsigned int* tgt_words) {
    if (threadIdx.x == 0) {
        g_acc[0] = 0.0;
        g_acc[1] = 0.0;
        // int64 little-endian values in [0,12): high 32-bit words all zero.
        int is64 = 1;
        for (int i = 0; i < 128; i++) {
            if (tgt_words[2 * i + 1] != 0u) { is64 = 0; break; }
        }
        g_is64 = is64;
    }
}

__device__ __forceinline__ int load_target(const void* t, int idx) {
    if (g_is64) return (int)((const long long*)t)[idx];
    return ((const int*)t)[idx];
}

// ---------------- K1: softmax -> masks, cross-entropy partial ----------------
__global__ void k1_masks(const float* __restrict__ pred, const void* __restrict__ tgt) {
    int pix = blockIdx.x * 256 + threadIdx.x;   // 0 .. Bz*HW-1
    int b = pix >> 16;
    int hw = pix & (HW - 1);
    const float* p = pred + (size_t)b * Cz * HW + hw;

    int t = load_target(tgt, pix);

    float v[Cz];
    float mx = -1e30f;
    float xt = 0.0f;
#pragma unroll
    for (int c = 0; c < Cz; c++) {
        v[c] = p[c * HW];
        mx = fmaxf(mx, v[c]);
        if (c == t) xt = v[c];
    }
    float s = 0.0f;
#pragma unroll
    for (int c = 0; c < Cz; c++) {
        v[c] = expf(v[c] - mx);
        s += v[c];
    }
    float inv = 1.0f / s;
#pragma unroll
    for (int c = 0; c < Cz; c++) {
        g_mask[(size_t)(b * Cz + c) * HW + hw] = (unsigned char)(v[c] * inv > 0.5f);
        g_mask[(size_t)(HALFM + b * Cz + c) * HW + hw] = (unsigned char)(c == t);
    }

    // log_softmax at target: x_t - max - log(sum exp)
    float logp = xt - mx - logf(s);

    // block reduction
    __shared__ float sred[256];
    sred[threadIdx.x] = logp;
    __syncthreads();
    for (int st = 128; st > 0; st >>= 1) {
        if (threadIdx.x < st) sred[threadIdx.x] += sred[threadIdx.x + st];
        __syncthreads();
    }
    if (threadIdx.x == 0) atomicAdd(&g_acc[1], (double)sred[0]);
}

// ---------------- K2: column 1D distance (both polarities) + has_fg ----------
// One block per mask, one thread per column w. Computes 1D distance along H
// to nearest feature (feature = ~mask for .x, = mask for .y), squares it and
// adds w^2 (the "a[j'] = g^2 + j'^2" precomputation for the row pass).
__global__ void k2_cols() {
    int m = blockIdx.x;
    int w = threadIdx.x;
    const unsigned char* msk = g_mask + (size_t)m * HW;
    float2* a = g_a + (size_t)m * HW;

    float c1 = LARGEF, c2 = LARGEF;
    int any = 0;
    for (int h = 0; h < Hh; h++) {
        int mv = msk[h * Ww + w];
        any |= mv;
        c1 = mv ? fminf(c1 + 1.0f, LARGEF) : 0.0f;   // feature = ~mask
        c2 = mv ? 0.0f : fminf(c2 + 1.0f, LARGEF);   // feature =  mask
        a[h * Ww + w] = make_float2(c1, c2);
    }
    c1 = LARGEF; c2 = LARGEF;
    float wf = (float)w;
    float w2 = wf * wf;
    for (int h = Hh - 1; h >= 0; h--) {
        int mv = msk[h * Ww + w];
        c1 = mv ? fminf(c1 + 1.0f, LARGEF) : 0.0f;
        c2 = mv ? 0.0f : fminf(c2 + 1.0f, LARGEF);
        float2 f = a[h * Ww + w];
        float gx = fminf(f.x, c1);
        float gy = fminf(f.y, c2);
        a[h * Ww + w] = make_float2(gx * gx + w2, gy * gy + w2);
    }

    __shared__ int sany[256];
    sany[w] = any;
    __syncthreads();
    for (int st = 128; st > 0; st >>= 1) {
        if (w < st) sany[w] |= sany[w + st];
        __syncthreads();
    }
    if (w == 0) g_hasfg[m] = sany[0];
}

// ---------------- K3: exact row pass + field = sqrt + sqrt -------------------
// grid (NMASK, Hh/RPB), 256 threads: 4 rows x 64 threads, 4 outputs/thread.
// D2[j] = min_j' ( a[j'] - 2*j*j' ) + j*j  , clamped at LARGE^2.
// Exact (integer fp32) on the finite path — matches reference bit-for-bit.
#define RPB 4
__global__ void k3_rows() {
    int m = blockIdx.x;
    int rg = blockIdx.y;
    int tid = threadIdx.x;
    __shared__ float2 srow[RPB][Ww];

    const float2* a = g_a + (size_t)m * HW + (size_t)rg * RPB * Ww;
    for (int i = tid; i < RPB * Ww; i += 256) {
        srow[i >> 8][i & (Ww - 1)] = a[i];
    }
    __syncthreads();

    int r = tid >> 6;            // 0..3   row within group
    int jq = tid & 63;           // 0..63
    int j0 = jq * 4;

    float m0 = -2.0f * (float)(j0 + 0);
    float m1 = -2.0f * (float)(j0 + 1);
    float m2 = -2.0f * (float)(j0 + 2);
    float m3 = -2.0f * (float)(j0 + 3);

    const float INF = __int_as_float(0x7f800000);
    float f0 = INF, f1 = INF, f2 = INF, f3 = INF;   // fg mins
    float b0 = INF, b1 = INF, b2 = INF, b3 = INF;   // bg mins

    float jpf = 0.0f;
#pragma unroll 4
    for (int jp = 0; jp < Ww; jp++) {
        float2 av = srow[r][jp];
        f0 = fminf(f0, fmaf(m0, jpf, av.x));
        f1 = fminf(f1, fmaf(m1, jpf, av.x));
        f2 = fminf(f2, fmaf(m2, jpf, av.x));
        f3 = fminf(f3, fmaf(m3, jpf, av.x));
        b0 = fminf(b0, fmaf(m0, jpf, av.y));
        b1 = fminf(b1, fmaf(m1, jpf, av.y));
        b2 = fminf(b2, fmaf(m2, jpf, av.y));
        b3 = fminf(b3, fmaf(m3, jpf, av.y));
        jpf += 1.0f;
    }

    int hf = g_hasfg[m];
    const float L2 = LARGEF * LARGEF;
    int h = rg * RPB + r;
    float* out = g_field + (size_t)m * HW + (size_t)h * Ww + j0;

    float fg[4] = {f0, f1, f2, f3};
    float bg[4] = {b0, b1, b2, b3};
#pragma unroll
    for (int k = 0; k < 4; k++) {
        float jf = (float)(j0 + k);
        float jj = jf * jf;
        float d2f = fminf(fg[k] + jj, L2);
        float d2b = fminf(bg[k] + jj, L2);
        float fld = hf ? (__fsqrt_rn(d2f) + __fsqrt_rn(d2b)) : 0.0f;
        out[k] = fld;
    }
}

// ---------------- K4: hausdorff loss reduction -------------------------------
__global__ void k4_loss(const float* __restrict__ pred, const void* __restrict__ tgt) {
    int pix = blockIdx.x * 256 + threadIdx.x;
    int b = pix >> 16;
    int hw = pix & (HW - 1);
    const float* p = pred + (size_t)b * Cz * HW + hw;

    int t = load_target(tgt, pix);

    float v[Cz];
    float mx = -1e30f;
#pragma unroll
    for (int c = 0; c < Cz; c++) {
        v[c] = p[c * HW];
        mx = fmaxf(mx, v[c]);
    }
    float s = 0.0f;
#pragma unroll
    for (int c = 0; c < Cz; c++) {
        v[c] = expf(v[c] - mx);
        s += v[c];
    }
    float inv = 1.0f / s;

    double acc = 0.0;
#pragma unroll
    for (int c = 0; c < Cz; c++) {
        float fP = g_field[(size_t)(b * Cz + c) * HW + hw];
        float fT = g_field[(size_t)(HALFM + b * Cz + c) * HW + hw];
        float dist = fP * fP + fT * fT;
        float e = v[c] * inv - ((c == t) ? 1.0f : 0.0f);
        acc += (double)(e * e * dist);
    }

    __shared__ double sred[256];
    sred[threadIdx.x] = acc;
    __syncthreads();
    for (int st = 128; st > 0; st >>= 1) {
        if (threadIdx.x < st) sred[threadIdx.x] += sred[threadIdx.x + st];
        __syncthreads();
    }
    if (threadIdx.x == 0) atomicAdd(&g_acc[0], sred[0]);
}

// ---------------- K5: finalize ----------------------------------------------
__global__ void k5_final(float* out) {
    if (threadIdx.x == 0) {
        double S  = g_acc[0];
        double CE = g_acc[1];
        double N = (double)Bz * (double)HW;       // elements per class / per CE
        double loss = S / N / (double)Cz / (double)Bz / 3.0 - CE / N;
        out[0] = (float)loss;
    }
}

// ---------------- launch -----------------------------------------------------
extern "C" void kernel_launch(void* const* d_in, const int* in_sizes, int n_in,
                              void* d_out, int out_size) {
    const float* pred = (const float*)d_in[0];
    const void*  tgt  = d_in[1];
    float* out = (float*)d_out;

    k0_init<<<1, 32>>>((const unsigned int*)tgt);
    k1_masks<<<(Bz * HW) / 256, 256>>>(pred, tgt);
    k2_cols<<<NMASK, 256>>>();
    k3_rows<<<dim3(NMASK, Hh / RPB), 256>>>();
    k4_loss<<<(Bz * HW) / 256, 256>>>(pred, tgt);
    k5_final<<<1, 32>>>(out);
    (void)in_sizes; (void)n_in; (void)out_size;
}